// round 13
// baseline (speedup 1.0000x reference)
#include <cuda_runtime.h>
#include <cuda_fp16.h>
#include <cstdint>

#define INSIZE 512
#define NREFL  64
#define BATCH  8192
#define NBLK   64

// ---------------- device scratch ----------------
__device__ float  g_sigma[INSIZE];
__device__ float  g_gram[2][64][64];
__device__ float  g_T[2][64][64];
__device__ float  g_C1[64 * 512];       // (Tu*Wu)*Sigma
__device__ float  g_Wvp[64 * 512];      // Tv*Wv~
__device__ float  g_E[512 * 64];        // Sigma*Wv~^T - Wu^T*(C1*Wv~^T)
__device__ __half g_MT[512 * 512];      // M^T fp16
__device__ __half g_xh[BATCH * INSIZE];

__device__ int          g_cnt;
__device__ volatile int g_sense;

// ---------------- helpers ----------------
__device__ __forceinline__ uint32_t smem_u32(const void* p) {
    uint32_t a;
    asm("{ .reg .u64 t; cvta.to.shared.u64 t, %1; cvt.u32.u64 %0, t; }" : "=r"(a) : "l"(p));
    return a;
}
__device__ __forceinline__ void cp_async16(uint32_t dst, const void* src) {
    asm volatile("cp.async.cg.shared.global [%0], [%1], 16;" :: "r"(dst), "l"(src) : "memory");
}
#define CP_COMMIT() asm volatile("cp.async.commit_group;" ::: "memory")
#define CP_WAIT1()  asm volatile("cp.async.wait_group 1;" ::: "memory")
#define SWZ64(o) ((o) ^ (((o) >> 3) & 0x30))

__device__ __forceinline__ void ldsm_x4(uint32_t* r, uint32_t addr) {
    asm volatile("ldmatrix.sync.aligned.m8n8.x4.shared.b16 {%0,%1,%2,%3}, [%4];"
                 : "=r"(r[0]), "=r"(r[1]), "=r"(r[2]), "=r"(r[3]) : "r"(addr));
}
__device__ __forceinline__ void mma16816(float* d, const uint32_t* a, const uint32_t* b) {
    asm volatile("mma.sync.aligned.m16n8k16.row.col.f32.f16.f16.f32 "
                 "{%0,%1,%2,%3}, {%4,%5,%6,%7}, {%8,%9}, {%0,%1,%2,%3};"
                 : "+f"(d[0]), "+f"(d[1]), "+f"(d[2]), "+f"(d[3])
                 : "r"(a[0]), "r"(a[1]), "r"(a[2]), "r"(a[3]), "r"(b[0]), "r"(b[1]));
}

// grid-wide barrier: all NBLK blocks co-resident (NBLK=64 < 148 SMs).
// target values 1..4 are distinct from both 0 (fresh) and 4 (post-replay),
// so state replays deterministically under CUDA graphs.
__device__ __forceinline__ void grid_barrier(int target) {
    __syncthreads();
    if (threadIdx.x == 0) {
        __threadfence();
        if (atomicAdd(&g_cnt, 1) == NBLK - 1) {
            g_cnt = 0;
            __threadfence();
            g_sense = target;
        } else {
            while (g_sense != target) __nanosleep(64);
            __threadfence();
        }
    }
    __syncthreads();
}

// ---------------------------------------------------------------------------
// conv_x: x fp32 -> fp16
// ---------------------------------------------------------------------------
__global__ __launch_bounds__(256)
void conv_x(const float4* __restrict__ x)
{
    const int i = blockIdx.x * 256 + threadIdx.x;
    float4 v = x[i];
    __half2* h = (__half2*)g_xh;
    h[i * 2 + 0] = __floats2half2_rn(v.x, v.y);
    h[i * 2 + 1] = __floats2half2_rn(v.z, v.w);
}

// ---------------------------------------------------------------------------
// prep_all: A gram+sigma | B tinv | C applyT | D c2+e | E buildM
// one launch, 4 grid barriers. 64 blocks x 256 threads, 64KB dyn smem.
// ---------------------------------------------------------------------------
#define PREP_SMEM 65536

__global__ __launch_bounds__(256)
void prep_all(const float* __restrict__ p,
              const float* __restrict__ U, const float* __restrict__ V)
{
    extern __shared__ __align__(16) float dyn[];
    const int bid = blockIdx.x, t = threadIdx.x;
    const int w = t >> 5, lane = t & 31;

    // ================= A: sigma + full grams =================
    if (bid == 0) {
        #pragma unroll
        for (int q = 0; q < 2; ++q) {
            const int i = t + q * 256;
            float s = 1.0f / (1.0f + expf(-p[i]));
            g_sigma[i] = 0.1f + 0.9f * s;
        }
    }
    #pragma unroll 1
    for (int q = 0; q < 16; ++q) {
        const int entry = (bid * 8 + w) * 16 + q;      // 0..8191
        const int mat = entry >> 12;
        const int e = entry & 4095;
        const int a = e >> 6, c = e & 63;
        const float* M = mat ? V : U;
        const float* ra = M + (size_t)a * 512;
        const float* rb = M + (size_t)c * 512;
        float ss = 0.f;
        #pragma unroll
        for (int j = lane; j < 512; j += 32) ss += ra[j] * rb[j];
        #pragma unroll
        for (int o = 16; o > 0; o >>= 1) ss += __shfl_xor_sync(0xffffffffu, ss, o);
        if (lane == 0) g_gram[mat][a][c] = ss;
    }
    grid_barrier(1);

    // ================= B: tinv (blocks 0..15, warp per column) =================
    if (bid < 16) {
        float* Gs = dyn;                       // [2][64][64] = 32KB
        for (int i = t; i < 8192; i += 256) Gs[i] = ((const float*)g_gram)[i];
        __syncthreads();
        const int task = bid * 8 + w;          // 0..127
        const int mat = task >> 6, c = task & 63;
        auto Lv = [&](int a, int m) -> float {
            if (mat == 0) return (a == m) ? Gs[(a << 6) + a] * 0.5f : Gs[(a << 6) + m];
            return (a == m) ? Gs[4096 + ((63 - a) << 6) + 63 - a] * 0.5f
                            : Gs[4096 + ((63 - a) << 6) + 63 - m];
        };
        float t0 = 0.f, t1 = 0.f;
        {
            const float inv = 1.0f / Lv(c, c);
            if (lane == c) t0 = inv;
            if (lane + 32 == c) t1 = inv;
        }
        for (int a = c - 1; a >= 0; --a) {
            float s = 0.f;
            if (lane > a && lane <= c)            s += Lv(a, lane) * t0;
            if (lane + 32 > a && lane + 32 <= c)  s += Lv(a, lane + 32) * t1;
            #pragma unroll
            for (int o = 16; o > 0; o >>= 1) s += __shfl_xor_sync(0xffffffffu, s, o);
            const float ta = -s / Lv(a, a);
            if (lane == a) t0 = ta;
            if (lane + 32 == a) t1 = ta;
        }
        g_T[mat][lane][c]      = t0;
        g_T[mat][lane + 32][c] = t1;
    }
    grid_barrier(2);

    // ================= C: C1 = (Tu*Wu)*Sigma ; Wvp = Tv*Wv~ =================
    {
        const int mat = bid >> 5;
        const int n0 = (bid & 31) * 16;
        float* Ts = dyn;                       // 16KB
        for (int i = t; i < 4096; i += 256) Ts[i] = (&g_T[mat][0][0])[i];
        __syncthreads();
        const int n = n0 + (t & 15);
        const int jg = t >> 4;                 // 16 groups of 4 rows
        float s[4] = {0.f, 0.f, 0.f, 0.f};
        #pragma unroll 4
        for (int k = 0; k < 64; ++k) {
            const float wv = mat ? __ldg(&V[(size_t)(63 - k) * 512 + n])
                                 : __ldg(&U[(size_t)k * 512 + n]);
            #pragma unroll
            for (int j = 0; j < 4; ++j)
                s[j] += Ts[(jg * 4 + j) * 64 + k] * wv;
        }
        const float sc = mat ? 1.0f : g_sigma[n];
        float* dst = mat ? g_Wvp : g_C1;
        #pragma unroll
        for (int j = 0; j < 4; ++j)
            dst[(size_t)(jg * 4 + j) * 512 + n] = s[j] * sc;
    }
    grid_barrier(3);

    // ================= D: per-b column C2 then E =================
    {
        float* Vv = dyn;                       // 512 floats
        float* c2 = dyn + 512;                 // 64 floats
        const int b = bid;
        #pragma unroll
        for (int q = 0; q < 2; ++q)
            Vv[t + q * 256] = __ldg(&V[(size_t)(63 - b) * 512 + t + q * 256]);
        __syncthreads();
        // C2[a][b] for a = w*8..w*8+7
        #pragma unroll 1
        for (int qa = 0; qa < 8; ++qa) {
            const int a = w * 8 + qa;
            const float* c1 = g_C1 + (size_t)a * 512;
            float ss = 0.f;
            #pragma unroll
            for (int j = lane; j < 512; j += 32) ss += c1[j] * Vv[j];
            #pragma unroll
            for (int o = 16; o > 0; o >>= 1) ss += __shfl_xor_sync(0xffffffffu, ss, o);
            if (lane == 0) c2[a] = ss;
        }
        __syncthreads();
        #pragma unroll
        for (int q = 0; q < 2; ++q) {
            const int i = t + q * 256;
            float s = g_sigma[i] * Vv[i];
            #pragma unroll 8
            for (int a = 0; a < 64; ++a)
                s -= __ldg(&U[(size_t)a * 512 + i]) * c2[a];
            g_E[(size_t)i * 64 + b] = s;
        }
    }
    grid_barrier(4);

    // ================= E: buildM tile 64x64 =================
    {
        float* Us  = dyn;            // [a][di]
        float* C1s = dyn + 4096;     // [a][dj]
        float* EsT = dyn + 8192;     // [b][di]
        float* Ws  = dyn + 12288;    // [b][dj]
        const int i0 = (bid & 7) * 64, j0 = (bid >> 3) * 64;
        for (int idx = t; idx < 4096; idx += 256) {
            const int a = idx >> 6, d = idx & 63;
            Us[idx]  = __ldg(&U[(size_t)a * 512 + i0 + d]);
            C1s[idx] = g_C1[(size_t)a * 512 + j0 + d];
            EsT[idx] = g_E[(size_t)(i0 + d) * 64 + a];
            Ws[idx]  = g_Wvp[(size_t)a * 512 + j0 + d];
        }
        __syncthreads();

        const int ti = t & 15, tj = t >> 4;
        float acc[4][4];
        #pragma unroll
        for (int r = 0; r < 4; ++r)
            #pragma unroll
            for (int c = 0; c < 4; ++c) acc[r][c] = 0.f;

        #pragma unroll 4
        for (int a = 0; a < 64; ++a) {
            float ua[4], c1[4];
            #pragma unroll
            for (int r = 0; r < 4; ++r) ua[r] = Us[a * 64 + ti * 4 + r];
            #pragma unroll
            for (int c = 0; c < 4; ++c) c1[c] = C1s[a * 64 + tj * 4 + c];
            #pragma unroll
            for (int r = 0; r < 4; ++r)
                #pragma unroll
                for (int c = 0; c < 4; ++c) acc[r][c] -= ua[r] * c1[c];
        }
        #pragma unroll 4
        for (int b = 0; b < 64; ++b) {
            float e[4], wv[4];
            #pragma unroll
            for (int r = 0; r < 4; ++r) e[r] = EsT[b * 64 + ti * 4 + r];
            #pragma unroll
            for (int c = 0; c < 4; ++c) wv[c] = Ws[b * 64 + tj * 4 + c];
            #pragma unroll
            for (int r = 0; r < 4; ++r)
                #pragma unroll
                for (int c = 0; c < 4; ++c) acc[r][c] -= e[r] * wv[c];
        }

        #pragma unroll
        for (int r = 0; r < 4; ++r) {
            const int i = i0 + ti * 4 + r;
            #pragma unroll
            for (int c = 0; c < 4; ++c) {
                const int j = j0 + tj * 4 + c;
                float m = acc[r][c] + (i == j ? g_sigma[i] : 0.f);
                g_MT[(size_t)j * 512 + i] = __float2half_rn(m);
            }
        }
    }
}

// ---------------------------------------------------------------------------
// GEMM (R9-validated): out = x_h * M + bias, K=512, CTA 128x128, 3 stages.
// ---------------------------------------------------------------------------
#define TM 128
#define TN 128
#define NKS 16
#define STG 16384

__global__ __launch_bounds__(256, 2)
void gemm_kernel(float* __restrict__ out, const float* __restrict__ bias)
{
    __shared__ __align__(1024) uint8_t smem[3 * STG];
    const uint32_t sbase = smem_u32(smem);
    const int t = threadIdx.x;
    const int lane = t & 31, wid = t >> 5;
    const int wm = wid & 3, wn = wid >> 2;
    const int m0 = blockIdx.x * TM, n0 = blockIdx.y * TN;

    float acc[2][8][4];
    #pragma unroll
    for (int fm = 0; fm < 2; ++fm)
        #pragma unroll
        for (int fn = 0; fn < 8; ++fn)
            #pragma unroll
            for (int j = 0; j < 4; ++j) acc[fm][fn][j] = 0.f;

    auto load_stage = [&](int st, int ks) {
        const __half* Ab = g_xh + (size_t)m0 * 512 + ks * 32;
        const __half* Bb = (const __half*)g_MT + (size_t)n0 * 512 + ks * 32;
        const uint32_t sA = sbase + st * STG;
        const uint32_t sB = sA + 8192;
        #pragma unroll
        for (int i = 0; i < 2; ++i) {
            const int idx = t + i * 256;
            const int row = idx >> 2, c = idx & 3;
            cp_async16(sA + SWZ64((uint32_t)(row * 64 + c * 16)),
                       Ab + (size_t)row * 512 + c * 8);
        }
        #pragma unroll
        for (int i = 0; i < 2; ++i) {
            const int idx = t + i * 256;
            const int row = idx >> 2, c = idx & 3;
            cp_async16(sB + SWZ64((uint32_t)(row * 64 + c * 16)),
                       Bb + (size_t)row * 512 + c * 8);
        }
    };

    auto compute_stage = [&](int st) {
        const uint32_t sA = sbase + st * STG;
        const uint32_t sB = sA + 8192;
        #pragma unroll
        for (int kf = 0; kf < 2; ++kf) {
            uint32_t a[2][4], b[4][4];
            #pragma unroll
            for (int fm = 0; fm < 2; ++fm) {
                const int row = wm * 32 + fm * 16 + (lane & 15);
                const int c   = kf * 2 + (lane >> 4);
                ldsm_x4(a[fm], sA + SWZ64((uint32_t)(row * 64 + c * 16)));
            }
            #pragma unroll
            for (int fp = 0; fp < 4; ++fp) {
                const int row = wn * 64 + fp * 16 + ((lane >> 4) << 3) + (lane & 7);
                const int c   = kf * 2 + ((lane >> 3) & 1);
                ldsm_x4(b[fp], sB + SWZ64((uint32_t)(row * 64 + c * 16)));
            }
            #pragma unroll
            for (int fm = 0; fm < 2; ++fm)
                #pragma unroll
                for (int fn = 0; fn < 8; ++fn)
                    mma16816(acc[fm][fn], a[fm], &b[fn >> 1][(fn & 1) * 2]);
        }
    };

    load_stage(0, 0); CP_COMMIT();
    load_stage(1, 1); CP_COMMIT();

    #pragma unroll 1
    for (int ks = 0; ks < NKS; ++ks) {
        CP_WAIT1();
        __syncthreads();
        const int kn = ks + 2;
        if (kn < NKS) load_stage(kn % 3, kn);
        CP_COMMIT();
        compute_stage(ks % 3);
    }

    #pragma unroll
    for (int fm = 0; fm < 2; ++fm) {
        const int r = m0 + wm * 32 + fm * 16 + (lane >> 2);
        #pragma unroll
        for (int fn = 0; fn < 8; ++fn) {
            const int cb = n0 + wn * 64 + fn * 8 + (lane & 3) * 2;
            const float2 bi = __ldg((const float2*)(bias + cb));
            float2 v0, v1;
            v0.x = acc[fm][fn][0] + bi.x; v0.y = acc[fm][fn][1] + bi.y;
            v1.x = acc[fm][fn][2] + bi.x; v1.y = acc[fm][fn][3] + bi.y;
            *(float2*)(out + (size_t)r * 512 + cb)       = v0;
            *(float2*)(out + (size_t)(r + 8) * 512 + cb) = v1;
        }
    }
}

// ---------------------------------------------------------------------------
extern "C" void kernel_launch(void* const* d_in, const int* in_sizes, int n_in,
                              void* d_out, int out_size)
{
    (void)in_sizes; (void)n_in; (void)out_size;
    const float* x    = (const float*)d_in[0];
    const float* p    = (const float*)d_in[1];
    const float* U    = (const float*)d_in[2];
    const float* V    = (const float*)d_in[3];
    const float* bias = (const float*)d_in[4];

    cudaFuncSetAttribute(prep_all, cudaFuncAttributeMaxDynamicSharedMemorySize,
                         PREP_SMEM);

    conv_x<<<BATCH * INSIZE / 4 / 256, 256>>>((const float4*)x);
    prep_all<<<NBLK, 256, PREP_SMEM>>>(p, U, V);
    gemm_kernel<<<dim3(BATCH / TM, 512 / TN), 256>>>((float*)d_out, bias);
}

// round 14
// speedup vs baseline: 1.3876x; 1.3876x over previous
#include <cuda_runtime.h>
#include <cuda_fp16.h>
#include <cstdint>

#define INSIZE 512
#define NREFL  64
#define BATCH  8192

// ---------------- device scratch ----------------
__device__ float  g_sigma[INSIZE];
__device__ float  g_gram[2][64][64];
__device__ float  g_T[2][64][64];       // T[row][col], app order
__device__ float  g_XG[64 * 64];        // XG[k][b] = sum_j U[k][j]*sig[j]*V[63-b][j]
__device__ __half g_MT[512 * 512];      // M^T fp16
__device__ __half g_xh[BATCH * INSIZE];

// ---------------- helpers ----------------
__device__ __forceinline__ uint32_t smem_u32(const void* p) {
    uint32_t a;
    asm("{ .reg .u64 t; cvta.to.shared.u64 t, %1; cvt.u32.u64 %0, t; }" : "=r"(a) : "l"(p));
    return a;
}
__device__ __forceinline__ void cp_async16(uint32_t dst, const void* src) {
    asm volatile("cp.async.cg.shared.global [%0], [%1], 16;" :: "r"(dst), "l"(src) : "memory");
}
#define CP_COMMIT() asm volatile("cp.async.commit_group;" ::: "memory")
#define CP_WAIT1()  asm volatile("cp.async.wait_group 1;" ::: "memory")
#define SWZ64(o) ((o) ^ (((o) >> 3) & 0x30))

__device__ __forceinline__ void ldsm_x4(uint32_t* r, uint32_t addr) {
    asm volatile("ldmatrix.sync.aligned.m8n8.x4.shared.b16 {%0,%1,%2,%3}, [%4];"
                 : "=r"(r[0]), "=r"(r[1]), "=r"(r[2]), "=r"(r[3]) : "r"(addr));
}
__device__ __forceinline__ void mma16816(float* d, const uint32_t* a, const uint32_t* b) {
    asm volatile("mma.sync.aligned.m16n8k16.row.col.f32.f16.f16.f32 "
                 "{%0,%1,%2,%3}, {%4,%5,%6,%7}, {%8,%9}, {%0,%1,%2,%3};"
                 : "+f"(d[0]), "+f"(d[1]), "+f"(d[2]), "+f"(d[3])
                 : "r"(a[0]), "r"(a[1]), "r"(a[2]), "r"(a[3]), "r"(b[0]), "r"(b[1]));
}
__device__ __forceinline__ float sigmoid_sig(float v) {
    return 0.1f + 0.9f * (1.0f / (1.0f + expf(-v)));
}

// ---------------------------------------------------------------------------
// K1: conv x->fp16 | grams | XG (sigma-weighted cross-gram). Also sigma->global.
// ---------------------------------------------------------------------------
__global__ __launch_bounds__(256)
void k1_kernel(const float4* __restrict__ x, const float* __restrict__ p,
               const float* __restrict__ U, const float* __restrict__ V)
{
    const int b = blockIdx.x, t = threadIdx.x;
    if (b < 4096) {
        if (b == 0) {               // sigma -> global (consumed by later launches)
            g_sigma[t]       = sigmoid_sig(p[t]);
            g_sigma[t + 256] = sigmoid_sig(p[t + 256]);
        }
        const int i = b * 256 + t;
        float4 v = x[i];
        __half2* h = (__half2*)g_xh;
        h[i * 2 + 0] = __floats2half2_rn(v.x, v.y);
        h[i * 2 + 1] = __floats2half2_rn(v.z, v.w);
    } else if (b < 5120) {
        // grams: warp per entry
        const int task = (b - 4096) * 8 + (t >> 5);   // 0..8191
        const int lane = t & 31;
        const int mat = task >> 12;
        const int e = task & 4095;
        const int a = e >> 6, c = e & 63;
        const float* M = mat ? V : U;
        const float* ra = M + (size_t)a * 512;
        const float* rb = M + (size_t)c * 512;
        float ss = 0.f;
        #pragma unroll
        for (int j = lane; j < 512; j += 32) ss += ra[j] * rb[j];
        #pragma unroll
        for (int o = 16; o > 0; o >>= 1) ss += __shfl_xor_sync(0xffffffffu, ss, o);
        if (lane == 0) g_gram[mat][a][c] = ss;
    } else {
        // XG[k][bb] = sum_j U[k][j] * sig[j] * V[63-bb][j]; warp per entry
        __shared__ float ssig[512];
        ssig[t]       = sigmoid_sig(p[t]);
        ssig[t + 256] = sigmoid_sig(p[t + 256]);
        __syncthreads();
        const int task = (b - 5120) * 8 + (t >> 5);   // 0..4095
        const int lane = t & 31;
        const int k = task >> 6, bb = task & 63;
        const float* ru = U + (size_t)k * 512;
        const float* rv = V + (size_t)(63 - bb) * 512;
        float ss = 0.f;
        #pragma unroll
        for (int j = lane; j < 512; j += 32) ss += ru[j] * ssig[j] * rv[j];
        #pragma unroll
        for (int o = 16; o > 0; o >>= 1) ss += __shfl_xor_sync(0xffffffffu, ss, o);
        if (lane == 0) g_XG[k * 64 + bb] = ss;
    }
}

// ---------------------------------------------------------------------------
// tinv (R12-proven): T = inv(D^-1 + strict_upper(Gram)). 4 blocks.
// ---------------------------------------------------------------------------
__global__ __launch_bounds__(1024)
void tinv_kernel()
{
    __shared__ float Gs[2][64][64];
    const int t = threadIdx.x;
    for (int i = t; i < 2 * 4096; i += 1024)
        ((float*)Gs)[i] = ((const float*)g_gram)[i];
    __syncthreads();

    const int w = t >> 5, lane = t & 31;
    const int task = w + 32 * blockIdx.x;      // 0..127
    const int mat = task >> 6, c = task & 63;
    auto Lv = [&](int a, int m) -> float {
        if (mat == 0) return (a == m) ? Gs[0][a][a] * 0.5f : Gs[0][a][m];
        return (a == m) ? Gs[1][63 - a][63 - a] * 0.5f : Gs[1][63 - a][63 - m];
    };
    float t0 = 0.f, t1 = 0.f;
    {
        const float inv = 1.0f / Lv(c, c);
        if (lane == c) t0 = inv;
        if (lane + 32 == c) t1 = inv;
    }
    for (int a = c - 1; a >= 0; --a) {
        float s = 0.f;
        if (lane > a && lane <= c)            s += Lv(a, lane) * t0;
        if (lane + 32 > a && lane + 32 <= c)  s += Lv(a, lane + 32) * t1;
        #pragma unroll
        for (int o = 16; o > 0; o >>= 1) s += __shfl_xor_sync(0xffffffffu, s, o);
        const float ta = -s / Lv(a, a);
        if (lane == a) t0 = ta;
        if (lane + 32 == a) t1 = ta;
    }
    g_T[mat][lane][c]      = t0;
    g_T[mat][lane + 32][c] = t1;
}

// ---------------------------------------------------------------------------
// fusedM: one block per 64x64 tile of M, all dependencies computed locally:
//   C2 = Tu*XG ; C1s = (Tu*Wu_slice)*sig_j ; Ws = Tv*Wv~_slice ;
//   E[b][di] = sig_i*V~[b][i] - sum_a Ul[a][di]*C2[a][b] ;
//   M = sig*I - Ul^T*C1s - E^T*Ws  -> g_MT fp16.
// smem regions (floats): R0..R6 x4096 + sig 128
// ---------------------------------------------------------------------------
#define FM_SMEM ((7 * 4096 + 128) * 4)

__global__ __launch_bounds__(256)
void fusedM_kernel(const float* __restrict__ U, const float* __restrict__ V)
{
    extern __shared__ __align__(16) float dyn[];
    float* R0 = dyn;               // TuT[k][a]  -> Ul[a][di]
    float* R1 = dyn + 4096;        // XG[k][b]   -> TvT[k][b] -> Vl[b][di]
    float* R2 = dyn + 8192;        // C2[a][b]
    float* R3 = dyn + 12288;       // W-slice staging [k][dj]
    float* R4 = dyn + 16384;       // C1s[a][dj]
    float* R5 = dyn + 20480;       // Ws[b][dj]
    float* R6 = dyn + 24576;       // E[b][di]
    float* sgi = dyn + 28672;      // sigma[i0+di]
    float* sgj = sgi + 64;         // sigma[j0+dj]

    const int t = threadIdx.x;
    const int ti = t & 15, tj = t >> 4;
    const int i0 = (blockIdx.x & 7) * 64, j0 = (blockIdx.x >> 3) * 64;

    // ---- load TuT (transposed), XG, sigma slices ----
    for (int idx = t; idx < 4096; idx += 256) {
        R0[(idx & 63) * 64 + (idx >> 6)] = (&g_T[0][0][0])[idx];  // TuT[k][a]=Tu[a][k]
        R1[idx] = g_XG[idx];
    }
    if (t < 64)        sgi[t] = g_sigma[i0 + t];
    else if (t < 128)  sgj[t - 64] = g_sigma[j0 + (t - 64)];
    __syncthreads();

    float acc[4][4];
    #define ZERO_ACC() { _Pragma("unroll") for (int r = 0; r < 4; ++r) \
                         _Pragma("unroll") for (int c = 0; c < 4; ++c) acc[r][c] = 0.f; }
    #define MM_STEP(Abuf, Bbuf, k) { float av[4], bv[4]; \
        _Pragma("unroll") for (int r = 0; r < 4; ++r) av[r] = (Abuf)[(k) * 64 + ti * 4 + r]; \
        _Pragma("unroll") for (int c = 0; c < 4; ++c) bv[c] = (Bbuf)[(k) * 64 + tj * 4 + c]; \
        _Pragma("unroll") for (int r = 0; r < 4; ++r) \
        _Pragma("unroll") for (int c = 0; c < 4; ++c) acc[r][c] += av[r] * bv[c]; }

    // ---- C2[a][b] = sum_k TuT[k][a] * XG[k][b] ----
    ZERO_ACC();
    #pragma unroll 4
    for (int k = 0; k < 64; ++k) MM_STEP(R0, R1, k);
    #pragma unroll
    for (int r = 0; r < 4; ++r)
        #pragma unroll
        for (int c = 0; c < 4; ++c)
            R2[(ti * 4 + r) * 64 + tj * 4 + c] = acc[r][c];
    __syncthreads();

    // ---- C1s[a][dj] = (sum_k TuT[k][a] * Wu[k][j0+dj]) * sig_j ----
    for (int idx = t; idx < 4096; idx += 256)
        R3[idx] = __ldg(&U[(size_t)(idx >> 6) * 512 + j0 + (idx & 63)]);
    __syncthreads();
    ZERO_ACC();
    #pragma unroll 4
    for (int k = 0; k < 64; ++k) MM_STEP(R0, R3, k);
    #pragma unroll
    for (int r = 0; r < 4; ++r)
        #pragma unroll
        for (int c = 0; c < 4; ++c)
            R4[(ti * 4 + r) * 64 + tj * 4 + c] = acc[r][c] * sgj[tj * 4 + c];
    __syncthreads();

    // ---- Ws[b][dj] = sum_k TvT[k][b] * Wv~[k][j0+dj] ----
    for (int idx = t; idx < 4096; idx += 256) {
        R1[(idx & 63) * 64 + (idx >> 6)] = (&g_T[1][0][0])[idx];  // TvT[k][b]
        R3[idx] = __ldg(&V[(size_t)(63 - (idx >> 6)) * 512 + j0 + (idx & 63)]);
    }
    __syncthreads();
    ZERO_ACC();
    #pragma unroll 4
    for (int k = 0; k < 64; ++k) MM_STEP(R1, R3, k);
    #pragma unroll
    for (int r = 0; r < 4; ++r)
        #pragma unroll
        for (int c = 0; c < 4; ++c)
            R5[(ti * 4 + r) * 64 + tj * 4 + c] = acc[r][c];
    __syncthreads();

    // ---- load Ul[a][di], Vl[b][di] (overwrite R0, R1) ----
    for (int idx = t; idx < 4096; idx += 256) {
        R0[idx] = __ldg(&U[(size_t)(idx >> 6) * 512 + i0 + (idx & 63)]);
        R1[idx] = __ldg(&V[(size_t)(63 - (idx >> 6)) * 512 + i0 + (idx & 63)]);
    }
    __syncthreads();

    // ---- E[b][di] = sig_i * Vl[b][di] - sum_a Ul[a][di] * C2[a][b] ----
    // thread tile: di = ti*4+r, b = tj*4+c
    ZERO_ACC();
    #pragma unroll 4
    for (int a = 0; a < 64; ++a) {
        float uv[4], c2v[4];
        #pragma unroll
        for (int r = 0; r < 4; ++r) uv[r] = R0[a * 64 + ti * 4 + r];
        #pragma unroll
        for (int c = 0; c < 4; ++c) c2v[c] = R2[a * 64 + tj * 4 + c];
        #pragma unroll
        for (int r = 0; r < 4; ++r)
            #pragma unroll
            for (int c = 0; c < 4; ++c) acc[r][c] += uv[r] * c2v[c];
    }
    #pragma unroll
    for (int r = 0; r < 4; ++r) {
        const int di = ti * 4 + r;
        #pragma unroll
        for (int c = 0; c < 4; ++c) {
            const int b = tj * 4 + c;
            R6[b * 64 + di] = sgi[di] * R1[b * 64 + di] - acc[r][c];
        }
    }
    __syncthreads();

    // ---- M[i][j] = sig_i*d_ij - sum_a Ul[a][di]*C1s[a][dj] - sum_b E[b][di]*Ws[b][dj]
    ZERO_ACC();
    #pragma unroll 4
    for (int a = 0; a < 64; ++a) {
        float uv[4], c1v[4];
        #pragma unroll
        for (int r = 0; r < 4; ++r) uv[r] = R0[a * 64 + ti * 4 + r];
        #pragma unroll
        for (int c = 0; c < 4; ++c) c1v[c] = R4[a * 64 + tj * 4 + c];
        #pragma unroll
        for (int r = 0; r < 4; ++r)
            #pragma unroll
            for (int c = 0; c < 4; ++c) acc[r][c] -= uv[r] * c1v[c];
    }
    #pragma unroll 4
    for (int b = 0; b < 64; ++b) {
        float ev[4], wv[4];
        #pragma unroll
        for (int r = 0; r < 4; ++r) ev[r] = R6[b * 64 + ti * 4 + r];
        #pragma unroll
        for (int c = 0; c < 4; ++c) wv[c] = R5[b * 64 + tj * 4 + c];
        #pragma unroll
        for (int r = 0; r < 4; ++r)
            #pragma unroll
            for (int c = 0; c < 4; ++c) acc[r][c] -= ev[r] * wv[c];
    }
    #pragma unroll
    for (int r = 0; r < 4; ++r) {
        const int i = i0 + ti * 4 + r;
        #pragma unroll
        for (int c = 0; c < 4; ++c) {
            const int j = j0 + tj * 4 + c;
            float m = acc[r][c] + (i == j ? sgi[ti * 4 + r] : 0.f);
            g_MT[(size_t)j * 512 + i] = __float2half_rn(m);
        }
    }
}

// ---------------------------------------------------------------------------
// GEMM (R9-proven): out = x_h * M + bias, K=512, CTA 128x128, 3 stages.
// ---------------------------------------------------------------------------
#define TM 128
#define TN 128
#define NKS 16
#define STG 16384

__global__ __launch_bounds__(256, 2)
void gemm_kernel(float* __restrict__ out, const float* __restrict__ bias)
{
    __shared__ __align__(1024) uint8_t smem[3 * STG];
    const uint32_t sbase = smem_u32(smem);
    const int t = threadIdx.x;
    const int lane = t & 31, wid = t >> 5;
    const int wm = wid & 3, wn = wid >> 2;
    const int m0 = blockIdx.x * TM, n0 = blockIdx.y * TN;

    float acc[2][8][4];
    #pragma unroll
    for (int fm = 0; fm < 2; ++fm)
        #pragma unroll
        for (int fn = 0; fn < 8; ++fn)
            #pragma unroll
            for (int j = 0; j < 4; ++j) acc[fm][fn][j] = 0.f;

    auto load_stage = [&](int st, int ks) {
        const __half* Ab = g_xh + (size_t)m0 * 512 + ks * 32;
        const __half* Bb = (const __half*)g_MT + (size_t)n0 * 512 + ks * 32;
        const uint32_t sA = sbase + st * STG;
        const uint32_t sB = sA + 8192;
        #pragma unroll
        for (int i = 0; i < 2; ++i) {
            const int idx = t + i * 256;
            const int row = idx >> 2, c = idx & 3;
            cp_async16(sA + SWZ64((uint32_t)(row * 64 + c * 16)),
                       Ab + (size_t)row * 512 + c * 8);
        }
        #pragma unroll
        for (int i = 0; i < 2; ++i) {
            const int idx = t + i * 256;
            const int row = idx >> 2, c = idx & 3;
            cp_async16(sB + SWZ64((uint32_t)(row * 64 + c * 16)),
                       Bb + (size_t)row * 512 + c * 8);
        }
    };

    auto compute_stage = [&](int st) {
        const uint32_t sA = sbase + st * STG;
        const uint32_t sB = sA + 8192;
        #pragma unroll
        for (int kf = 0; kf < 2; ++kf) {
            uint32_t a[2][4], b[4][4];
            #pragma unroll
            for (int fm = 0; fm < 2; ++fm) {
                const int row = wm * 32 + fm * 16 + (lane & 15);
                const int c   = kf * 2 + (lane >> 4);
                ldsm_x4(a[fm], sA + SWZ64((uint32_t)(row * 64 + c * 16)));
            }
            #pragma unroll
            for (int fp = 0; fp < 4; ++fp) {
                const int row = wn * 64 + fp * 16 + ((lane >> 4) << 3) + (lane & 7);
                const int c   = kf * 2 + ((lane >> 3) & 1);
                ldsm_x4(b[fp], sB + SWZ64((uint32_t)(row * 64 + c * 16)));
            }
            #pragma unroll
            for (int fm = 0; fm < 2; ++fm)
                #pragma unroll
                for (int fn = 0; fn < 8; ++fn)
                    mma16816(acc[fm][fn], a[fm], &b[fn >> 1][(fn & 1) * 2]);
        }
    };

    load_stage(0, 0); CP_COMMIT();
    load_stage(1, 1); CP_COMMIT();

    #pragma unroll 1
    for (int ks = 0; ks < NKS; ++ks) {
        CP_WAIT1();
        __syncthreads();
        const int kn = ks + 2;
        if (kn < NKS) load_stage(kn % 3, kn);
        CP_COMMIT();
        compute_stage(ks % 3);
    }

    #pragma unroll
    for (int fm = 0; fm < 2; ++fm) {
        const int r = m0 + wm * 32 + fm * 16 + (lane >> 2);
        #pragma unroll
        for (int fn = 0; fn < 8; ++fn) {
            const int cb = n0 + wn * 64 + fn * 8 + (lane & 3) * 2;
            const float2 bi = __ldg((const float2*)(bias + cb));
            float2 v0, v1;
            v0.x = acc[fm][fn][0] + bi.x; v0.y = acc[fm][fn][1] + bi.y;
            v1.x = acc[fm][fn][2] + bi.x; v1.y = acc[fm][fn][3] + bi.y;
            *(float2*)(out + (size_t)r * 512 + cb)       = v0;
            *(float2*)(out + (size_t)(r + 8) * 512 + cb) = v1;
        }
    }
}

// ---------------------------------------------------------------------------
extern "C" void kernel_launch(void* const* d_in, const int* in_sizes, int n_in,
                              void* d_out, int out_size)
{
    (void)in_sizes; (void)n_in; (void)out_size;
    const float* x    = (const float*)d_in[0];
    const float* p    = (const float*)d_in[1];
    const float* U    = (const float*)d_in[2];
    const float* V    = (const float*)d_in[3];
    const float* bias = (const float*)d_in[4];

    cudaFuncSetAttribute(fusedM_kernel, cudaFuncAttributeMaxDynamicSharedMemorySize,
                         FM_SMEM);

    k1_kernel<<<4096 + 1024 + 512, 256>>>((const float4*)x, p, U, V);
    tinv_kernel<<<4, 1024>>>();
    fusedM_kernel<<<64, 256, FM_SMEM>>>(U, V);
    gemm_kernel<<<dim3(BATCH / TM, 512 / TN), 256>>>((float*)d_out, bias);
}

// round 15
// speedup vs baseline: 1.4639x; 1.0550x over previous
#include <cuda_runtime.h>
#include <cuda_fp16.h>
#include <cstdint>

#define INSIZE 512
#define NREFL  64
#define BATCH  8192

// ---------------- device scratch ----------------
__device__ float  g_sigma[INSIZE];
__device__ float  g_gram[2][64][64];
__device__ float  g_T[2][64][64];       // T[row][col], app order
__device__ float  g_XG[64 * 64];        // XG[k][b] = sum_j U[k][j]*sig[j]*V[63-b][j]
__device__ __half g_MT[512 * 512];      // M^T fp16
__device__ __half g_xh[BATCH * INSIZE];

// ---------------- helpers ----------------
__device__ __forceinline__ uint32_t smem_u32(const void* p) {
    uint32_t a;
    asm("{ .reg .u64 t; cvta.to.shared.u64 t, %1; cvt.u32.u64 %0, t; }" : "=r"(a) : "l"(p));
    return a;
}
__device__ __forceinline__ void cp_async16(uint32_t dst, const void* src) {
    asm volatile("cp.async.cg.shared.global [%0], [%1], 16;" :: "r"(dst), "l"(src) : "memory");
}
#define CP_COMMIT() asm volatile("cp.async.commit_group;" ::: "memory")
#define CP_WAIT1()  asm volatile("cp.async.wait_group 1;" ::: "memory")
#define SWZ64(o) ((o) ^ (((o) >> 3) & 0x30))

__device__ __forceinline__ void ldsm_x4(uint32_t* r, uint32_t addr) {
    asm volatile("ldmatrix.sync.aligned.m8n8.x4.shared.b16 {%0,%1,%2,%3}, [%4];"
                 : "=r"(r[0]), "=r"(r[1]), "=r"(r[2]), "=r"(r[3]) : "r"(addr));
}
__device__ __forceinline__ void mma16816(float* d, const uint32_t* a, const uint32_t* b) {
    asm volatile("mma.sync.aligned.m16n8k16.row.col.f32.f16.f16.f32 "
                 "{%0,%1,%2,%3}, {%4,%5,%6,%7}, {%8,%9}, {%0,%1,%2,%3};"
                 : "+f"(d[0]), "+f"(d[1]), "+f"(d[2]), "+f"(d[3])
                 : "r"(a[0]), "r"(a[1]), "r"(a[2]), "r"(a[3]), "r"(b[0]), "r"(b[1]));
}
__device__ __forceinline__ float sigmoid_sig(float v) {
    return 0.1f + 0.9f * (1.0f / (1.0f + expf(-v)));
}
__device__ __forceinline__ float dot4(float4 a, float4 b) {
    return a.x * b.x + a.y * b.y + a.z * b.z + a.w * b.w;
}

// ---------------------------------------------------------------------------
// K1: conv x->fp16 | grams | XG. sigma -> global. float4 dot paths.
// ---------------------------------------------------------------------------
__global__ __launch_bounds__(256)
void k1_kernel(const float4* __restrict__ x, const float* __restrict__ p,
               const float* __restrict__ U, const float* __restrict__ V)
{
    const int b = blockIdx.x, t = threadIdx.x;
    if (b < 4096) {
        if (b == 0) {
            g_sigma[t]       = sigmoid_sig(p[t]);
            g_sigma[t + 256] = sigmoid_sig(p[t + 256]);
        }
        const int i = b * 256 + t;
        float4 v = x[i];
        __half2* h = (__half2*)g_xh;
        h[i * 2 + 0] = __floats2half2_rn(v.x, v.y);
        h[i * 2 + 1] = __floats2half2_rn(v.z, v.w);
    } else if (b < 5120) {
        // grams: warp per entry, float4 loads
        const int task = (b - 4096) * 8 + (t >> 5);
        const int lane = t & 31;
        const int mat = task >> 12;
        const int e = task & 4095;
        const int a = e >> 6, c = e & 63;
        const float* M = mat ? V : U;
        const float4* ra = (const float4*)(M + (size_t)a * 512);
        const float4* rb = (const float4*)(M + (size_t)c * 512);
        float ss = 0.f;
        #pragma unroll
        for (int j = lane; j < 128; j += 32)
            ss += dot4(__ldg(&ra[j]), __ldg(&rb[j]));
        #pragma unroll
        for (int o = 16; o > 0; o >>= 1) ss += __shfl_xor_sync(0xffffffffu, ss, o);
        if (lane == 0) g_gram[mat][a][c] = ss;
    } else {
        // XG[k][bb] = sum_j U[k][j]*sig[j]*V[63-bb][j]
        __shared__ float ssig[512];
        ssig[t]       = sigmoid_sig(p[t]);
        ssig[t + 256] = sigmoid_sig(p[t + 256]);
        __syncthreads();
        const int task = (b - 5120) * 8 + (t >> 5);
        const int lane = t & 31;
        const int k = task >> 6, bb = task & 63;
        const float4* ru = (const float4*)(U + (size_t)k * 512);
        const float4* rv = (const float4*)(V + (size_t)(63 - bb) * 512);
        const float4* sg = (const float4*)ssig;
        float ss = 0.f;
        #pragma unroll
        for (int j = lane; j < 128; j += 32) {
            float4 a4 = __ldg(&ru[j]), b4 = __ldg(&rv[j]), s4 = sg[j];
            ss += a4.x * s4.x * b4.x + a4.y * s4.y * b4.y
                + a4.z * s4.z * b4.z + a4.w * s4.w * b4.w;
        }
        #pragma unroll
        for (int o = 16; o > 0; o >>= 1) ss += __shfl_xor_sync(0xffffffffu, ss, o);
        if (lane == 0) g_XG[k * 64 + bb] = ss;
    }
}

// ---------------------------------------------------------------------------
// tinv (proven): T = inv(D^-1 + strict_upper(Gram)). 4 blocks.
// ---------------------------------------------------------------------------
__global__ __launch_bounds__(1024)
void tinv_kernel()
{
    __shared__ float Gs[2][64][64];
    const int t = threadIdx.x;
    for (int i = t; i < 2 * 4096; i += 1024)
        ((float*)Gs)[i] = ((const float*)g_gram)[i];
    __syncthreads();

    const int w = t >> 5, lane = t & 31;
    const int task = w + 32 * blockIdx.x;
    const int mat = task >> 6, c = task & 63;
    auto Lv = [&](int a, int m) -> float {
        if (mat == 0) return (a == m) ? Gs[0][a][a] * 0.5f : Gs[0][a][m];
        return (a == m) ? Gs[1][63 - a][63 - a] * 0.5f : Gs[1][63 - a][63 - m];
    };
    float t0 = 0.f, t1 = 0.f;
    {
        const float inv = 1.0f / Lv(c, c);
        if (lane == c) t0 = inv;
        if (lane + 32 == c) t1 = inv;
    }
    for (int a = c - 1; a >= 0; --a) {
        float s = 0.f;
        if (lane > a && lane <= c)            s += Lv(a, lane) * t0;
        if (lane + 32 > a && lane + 32 <= c)  s += Lv(a, lane + 32) * t1;
        #pragma unroll
        for (int o = 16; o > 0; o >>= 1) s += __shfl_xor_sync(0xffffffffu, s, o);
        const float ta = -s / Lv(a, a);
        if (lane == a) t0 = ta;
        if (lane + 32 == a) t1 = ta;
    }
    g_T[mat][lane][c]      = t0;
    g_T[mat][lane + 32][c] = t1;
}

// ---------------------------------------------------------------------------
// fusedM: block per 64x64 tile of M; all small mms local; float4 LDS/STS.
// ---------------------------------------------------------------------------
#define FM_SMEM ((7 * 4096 + 128) * 4)

__global__ __launch_bounds__(256)
void fusedM_kernel(const float* __restrict__ U, const float* __restrict__ V)
{
    extern __shared__ __align__(16) float dyn[];
    float* R0 = dyn;               // TuT[k][a]  -> Ul[a][di]
    float* R1 = dyn + 4096;        // XG[k][b]   -> TvT[k][b] -> Vl[b][di]
    float* R2 = dyn + 8192;        // C2[a][b]
    float* R3 = dyn + 12288;       // W-slice staging [k][dj]
    float* R4 = dyn + 16384;       // C1s[a][dj]
    float* R5 = dyn + 20480;       // Ws[b][dj]
    float* R6 = dyn + 24576;       // E[b][di]
    float* sgi = dyn + 28672;
    float* sgj = sgi + 64;

    const int t = threadIdx.x;
    const int ti = t & 15, tj = t >> 4;
    const int i0 = (blockIdx.x & 7) * 64, j0 = (blockIdx.x >> 3) * 64;

    // ---- load TuT (scalar transpose), XG (float4), sigma ----
    for (int idx = t; idx < 4096; idx += 256)
        R0[(idx & 63) * 64 + (idx >> 6)] = (&g_T[0][0][0])[idx];
    for (int idx = t; idx < 1024; idx += 256)
        ((float4*)R1)[idx] = ((const float4*)g_XG)[idx];
    if (t < 64)        sgi[t] = g_sigma[i0 + t];
    else if (t < 128)  sgj[t - 64] = g_sigma[j0 + (t - 64)];
    __syncthreads();

    float acc[4][4];
    #define ZERO_ACC() { _Pragma("unroll") for (int r = 0; r < 4; ++r) \
                         _Pragma("unroll") for (int c = 0; c < 4; ++c) acc[r][c] = 0.f; }
    #define MM_STEP(Abuf, Bbuf, k) { \
        float4 av = *(const float4*)&(Abuf)[(k) * 64 + ti * 4]; \
        float4 bv = *(const float4*)&(Bbuf)[(k) * 64 + tj * 4]; \
        const float aa[4] = { av.x, av.y, av.z, av.w }; \
        const float bb[4] = { bv.x, bv.y, bv.z, bv.w }; \
        _Pragma("unroll") for (int r = 0; r < 4; ++r) \
        _Pragma("unroll") for (int c = 0; c < 4; ++c) acc[r][c] += aa[r] * bb[c]; }

    // ---- C2[a][b] = sum_k TuT[k][a] * XG[k][b] ----
    ZERO_ACC();
    #pragma unroll 4
    for (int k = 0; k < 64; ++k) MM_STEP(R0, R1, k);
    #pragma unroll
    for (int r = 0; r < 4; ++r)
        *(float4*)&R2[(ti * 4 + r) * 64 + tj * 4]
            = make_float4(acc[r][0], acc[r][1], acc[r][2], acc[r][3]);
    __syncthreads();

    // ---- C1s[a][dj] = (sum_k TuT[k][a] * Wu[k][j0+dj]) * sig_j ----
    for (int idx = t; idx < 1024; idx += 256) {
        const int row = idx >> 4, c4 = idx & 15;
        *(float4*)&R3[row * 64 + c4 * 4]
            = __ldg((const float4*)&U[(size_t)row * 512 + j0 + c4 * 4]);
    }
    __syncthreads();
    ZERO_ACC();
    #pragma unroll 4
    for (int k = 0; k < 64; ++k) MM_STEP(R0, R3, k);
    {
        const float s0 = sgj[tj * 4], s1 = sgj[tj * 4 + 1];
        const float s2 = sgj[tj * 4 + 2], s3 = sgj[tj * 4 + 3];
        #pragma unroll
        for (int r = 0; r < 4; ++r)
            *(float4*)&R4[(ti * 4 + r) * 64 + tj * 4]
                = make_float4(acc[r][0] * s0, acc[r][1] * s1, acc[r][2] * s2, acc[r][3] * s3);
    }
    __syncthreads();

    // ---- Ws[b][dj] = sum_k TvT[k][b] * Wv~[k][j0+dj] ----
    for (int idx = t; idx < 4096; idx += 256)
        R1[(idx & 63) * 64 + (idx >> 6)] = (&g_T[1][0][0])[idx];
    for (int idx = t; idx < 1024; idx += 256) {
        const int row = idx >> 4, c4 = idx & 15;
        *(float4*)&R3[row * 64 + c4 * 4]
            = __ldg((const float4*)&V[(size_t)(63 - row) * 512 + j0 + c4 * 4]);
    }
    __syncthreads();
    ZERO_ACC();
    #pragma unroll 4
    for (int k = 0; k < 64; ++k) MM_STEP(R1, R3, k);
    #pragma unroll
    for (int r = 0; r < 4; ++r)
        *(float4*)&R5[(ti * 4 + r) * 64 + tj * 4]
            = make_float4(acc[r][0], acc[r][1], acc[r][2], acc[r][3]);
    __syncthreads();

    // ---- load Ul[a][di], Vl[b][di] (float4, overwrite R0, R1) ----
    for (int idx = t; idx < 1024; idx += 256) {
        const int row = idx >> 4, c4 = idx & 15;
        *(float4*)&R0[row * 64 + c4 * 4]
            = __ldg((const float4*)&U[(size_t)row * 512 + i0 + c4 * 4]);
        *(float4*)&R1[row * 64 + c4 * 4]
            = __ldg((const float4*)&V[(size_t)(63 - row) * 512 + i0 + c4 * 4]);
    }
    __syncthreads();

    // ---- E[b][di] = sig_i * Vl[b][di] - sum_a Ul[a][di] * C2[a][b] ----
    ZERO_ACC();
    #pragma unroll 4
    for (int a = 0; a < 64; ++a) MM_STEP(R0, R2, a);
    {
        const float s0 = sgi[ti * 4], s1 = sgi[ti * 4 + 1];
        const float s2 = sgi[ti * 4 + 2], s3 = sgi[ti * 4 + 3];
        #pragma unroll
        for (int c = 0; c < 4; ++c) {
            const int b = tj * 4 + c;
            float4 vl = *(const float4*)&R1[b * 64 + ti * 4];
            *(float4*)&R6[b * 64 + ti * 4]
                = make_float4(s0 * vl.x - acc[0][c], s1 * vl.y - acc[1][c],
                              s2 * vl.z - acc[2][c], s3 * vl.w - acc[3][c]);
        }
    }
    __syncthreads();

    // ---- M = sig*I - Ul^T*C1s - E^T*Ws ----
    ZERO_ACC();
    #pragma unroll 4
    for (int a = 0; a < 64; ++a) MM_STEP(R0, R4, a);
    #pragma unroll 4
    for (int b = 0; b < 64; ++b) MM_STEP(R6, R5, b);
    #pragma unroll
    for (int c = 0; c < 4; ++c) {
        const int j = j0 + tj * 4 + c;
        float m[4];
        #pragma unroll
        for (int r = 0; r < 4; ++r) {
            const int i = i0 + ti * 4 + r;
            m[r] = -acc[r][c] + (i == j ? sgi[ti * 4 + r] : 0.f);
        }
        __half* dst = &g_MT[(size_t)j * 512 + i0 + ti * 4];
        *(__half2*)(dst)     = __floats2half2_rn(m[0], m[1]);
        *(__half2*)(dst + 2) = __floats2half2_rn(m[2], m[3]);
    }
}

// ---------------------------------------------------------------------------
// GEMM (proven): out = x_h * M + bias, K=512, CTA 128x128, 3 stages.
// ---------------------------------------------------------------------------
#define TM 128
#define TN 128
#define NKS 16
#define STG 16384

__global__ __launch_bounds__(256, 2)
void gemm_kernel(float* __restrict__ out, const float* __restrict__ bias)
{
    __shared__ __align__(1024) uint8_t smem[3 * STG];
    const uint32_t sbase = smem_u32(smem);
    const int t = threadIdx.x;
    const int lane = t & 31, wid = t >> 5;
    const int wm = wid & 3, wn = wid >> 2;
    const int m0 = blockIdx.x * TM, n0 = blockIdx.y * TN;

    float acc[2][8][4];
    #pragma unroll
    for (int fm = 0; fm < 2; ++fm)
        #pragma unroll
        for (int fn = 0; fn < 8; ++fn)
            #pragma unroll
            for (int j = 0; j < 4; ++j) acc[fm][fn][j] = 0.f;

    auto load_stage = [&](int st, int ks) {
        const __half* Ab = g_xh + (size_t)m0 * 512 + ks * 32;
        const __half* Bb = (const __half*)g_MT + (size_t)n0 * 512 + ks * 32;
        const uint32_t sA = sbase + st * STG;
        const uint32_t sB = sA + 8192;
        #pragma unroll
        for (int i = 0; i < 2; ++i) {
            const int idx = t + i * 256;
            const int row = idx >> 2, c = idx & 3;
            cp_async16(sA + SWZ64((uint32_t)(row * 64 + c * 16)),
                       Ab + (size_t)row * 512 + c * 8);
        }
        #pragma unroll
        for (int i = 0; i < 2; ++i) {
            const int idx = t + i * 256;
            const int row = idx >> 2, c = idx & 3;
            cp_async16(sB + SWZ64((uint32_t)(row * 64 + c * 16)),
                       Bb + (size_t)row * 512 + c * 8);
        }
    };

    auto compute_stage = [&](int st) {
        const uint32_t sA = sbase + st * STG;
        const uint32_t sB = sA + 8192;
        #pragma unroll
        for (int kf = 0; kf < 2; ++kf) {
            uint32_t a[2][4], b[4][4];
            #pragma unroll
            for (int fm = 0; fm < 2; ++fm) {
                const int row = wm * 32 + fm * 16 + (lane & 15);
                const int c   = kf * 2 + (lane >> 4);
                ldsm_x4(a[fm], sA + SWZ64((uint32_t)(row * 64 + c * 16)));
            }
            #pragma unroll
            for (int fp = 0; fp < 4; ++fp) {
                const int row = wn * 64 + fp * 16 + ((lane >> 4) << 3) + (lane & 7);
                const int c   = kf * 2 + ((lane >> 3) & 1);
                ldsm_x4(b[fp], sB + SWZ64((uint32_t)(row * 64 + c * 16)));
            }
            #pragma unroll
            for (int fm = 0; fm < 2; ++fm)
                #pragma unroll
                for (int fn = 0; fn < 8; ++fn)
                    mma16816(acc[fm][fn], a[fm], &b[fn >> 1][(fn & 1) * 2]);
        }
    };

    load_stage(0, 0); CP_COMMIT();
    load_stage(1, 1); CP_COMMIT();

    #pragma unroll 1
    for (int ks = 0; ks < NKS; ++ks) {
        CP_WAIT1();
        __syncthreads();
        const int kn = ks + 2;
        if (kn < NKS) load_stage(kn % 3, kn);
        CP_COMMIT();
        compute_stage(ks % 3);
    }

    #pragma unroll
    for (int fm = 0; fm < 2; ++fm) {
        const int r = m0 + wm * 32 + fm * 16 + (lane >> 2);
        #pragma unroll
        for (int fn = 0; fn < 8; ++fn) {
            const int cb = n0 + wn * 64 + fn * 8 + (lane & 3) * 2;
            const float2 bi = __ldg((const float2*)(bias + cb));
            float2 v0, v1;
            v0.x = acc[fm][fn][0] + bi.x; v0.y = acc[fm][fn][1] + bi.y;
            v1.x = acc[fm][fn][2] + bi.x; v1.y = acc[fm][fn][3] + bi.y;
            *(float2*)(out + (size_t)r * 512 + cb)       = v0;
            *(float2*)(out + (size_t)(r + 8) * 512 + cb) = v1;
        }
    }
}

// ---------------------------------------------------------------------------
extern "C" void kernel_launch(void* const* d_in, const int* in_sizes, int n_in,
                              void* d_out, int out_size)
{
    (void)in_sizes; (void)n_in; (void)out_size;
    const float* x    = (const float*)d_in[0];
    const float* p    = (const float*)d_in[1];
    const float* U    = (const float*)d_in[2];
    const float* V    = (const float*)d_in[3];
    const float* bias = (const float*)d_in[4];

    cudaFuncSetAttribute(fusedM_kernel, cudaFuncAttributeMaxDynamicSharedMemorySize,
                         FM_SMEM);

    k1_kernel<<<4096 + 1024 + 512, 256>>>((const float4*)x, p, U, V);
    tinv_kernel<<<4, 1024>>>();
    fusedM_kernel<<<64, 256, FM_SMEM>>>(U, V);
    gemm_kernel<<<dim3(BATCH / TM, 512 / TN), 256>>>((float*)d_out, bias);
}